// round 13
// baseline (speedup 1.0000x reference)
#include <cuda_runtime.h>
#include <cstdint>

#define BATCH 16384
#define D     1024
#define LN_EPS 1e-5f
#define GSPLIT 8          // split-K for G = x^T x
#define HSPLIT 4          // split-K for hebb = Wf * G

// ---------------- scratch (static device globals; no runtime alloc) ----------
__device__ __align__(16) float g_xc  [(size_t)BATCH * D];     // x rounded to tf32
__device__ __align__(16) float g_wsc [(size_t)D * D];         // W_slow rounded
__device__ __align__(16) float g_wfc [(size_t)D * D];         // W_fast rounded
__device__ __align__(16) float g_fast[(size_t)BATCH * D];     // fast, fp32
__device__ __align__(16) float g_part[(size_t)GSPLIT * D * D];// split-K partials (G, then hebb)
__device__ __align__(16) float g_G   [(size_t)D * D];         // G = x^T x (full, tf32)
__device__ float g_msq_part[64 * D];
__device__ float g_msq[D];
__device__ float g_efflr[1];

// ---------------- helpers ----------------------------------------------------
__device__ __forceinline__ unsigned tf32u(float x) {
    unsigned r;
    asm("cvt.rna.tf32.f32 %0, %1;" : "=r"(r) : "f"(x));
    return r;
}
__device__ __forceinline__ unsigned fu(float x) { return __float_as_uint(x); }

__device__ __forceinline__ void mma8(float c[4],
                                     unsigned a0, unsigned a1, unsigned a2, unsigned a3,
                                     unsigned b0, unsigned b1) {
    asm volatile(
        "mma.sync.aligned.m16n8k8.row.col.f32.tf32.tf32.f32 "
        "{%0,%1,%2,%3}, {%4,%5,%6,%7}, {%8,%9}, {%0,%1,%2,%3};\n"
        : "+f"(c[0]), "+f"(c[1]), "+f"(c[2]), "+f"(c[3])
        : "r"(a0), "r"(a1), "r"(a2), "r"(a3), "r"(b0), "r"(b1));
}

__device__ __forceinline__ void cpa16(void* dst, const void* src) {
    unsigned sd = (unsigned)__cvta_generic_to_shared(dst);
    asm volatile("cp.async.cg.shared.global [%0], [%1], 16;\n" :: "r"(sd), "l"(src));
}
#define CP_COMMIT() asm volatile("cp.async.commit_group;\n" ::: "memory")
#define CP_WAIT0()  asm volatile("cp.async.wait_group 0;\n" ::: "memory")
#define CP_WAIT1()  asm volatile("cp.async.wait_group 1;\n" ::: "memory")

__device__ __forceinline__ float warpSum(float v) {
    #pragma unroll
    for (int o = 16; o > 0; o >>= 1) v += __shfl_xor_sync(0xffffffffu, v, o);
    return v;
}

// ============================================================================
// Pre-convert: round fp32 -> tf32 (rna) once, in gmem
// ============================================================================
__global__ void cvt_rna_kernel(const float4* __restrict__ s, float4* __restrict__ d, int n4) {
    int i  = blockIdx.x * 256 + threadIdx.x;
    int st = gridDim.x * 256;
    for (; i < n4; i += st) {
        float4 v = s[i];
        v.x = __uint_as_float(tf32u(v.x));
        v.y = __uint_as_float(tf32u(v.y));
        v.z = __uint_as_float(tf32u(v.z));
        v.w = __uint_as_float(tf32u(v.w));
        d[i] = v;
    }
}

// ============================================================================
// TN GEMM (mma.sync tf32): C[m][n] = sum_k A[m][k] * B[n][k]
// 128x128 block tile, 4 warps (2x2 of 64x64), BK=16, 3-stage cp.async ring.
// COMP is software-pipelined at n-column granularity: per jn group, 2 LDS
// (b[jn+2]) are issued right before 4 HMMAs of column jn, so the tensor pipe
// stays fed during smem traffic instead of the bulk-LDS / bulk-MMA phasing
// that left it 50% idle.
// ============================================================================
#define RST 3
#define SPITCH 20                       // floats per smem row (pad 16->20)
#define STG_F (128 * SPITCH)            // 2560 floats per tile buffer
#define SMEM_DYN (RST * 2 * STG_F * 4)  // 61440 bytes

__global__ __launch_bounds__(128, 2)
void gemm_mma(const float* __restrict__ A, const float* __restrict__ B,
              float* __restrict__ C, int ldk, int kchunk, long long czstride) {
    extern __shared__ float sm[];

    const int tid  = threadIdx.x;
    const int warp = tid >> 5, lane = tid & 31;
    const int g = lane >> 2, tg = lane & 3;
    const int wm = (warp >> 1) * 64;
    const int wn = (warp & 1) * 64;

    const int m0 = blockIdx.y * 128, n0 = blockIdx.x * 128;
    const int kbase = blockIdx.z * kchunk;

    const float* __restrict__ Ab = A + (size_t)m0 * ldk + kbase;
    const float* __restrict__ Bb = B + (size_t)n0 * ldk + kbase;

    float acc[4][8][4];
    #pragma unroll
    for (int i = 0; i < 4; i++)
        #pragma unroll
        for (int j = 0; j < 8; j++)
            #pragma unroll
            for (int q = 0; q < 4; q++) acc[i][j][q] = 0.f;

    const int lr = tid >> 2;          // 0..31
    const int lc = (tid & 3) << 2;    // 0,4,8,12

    auto LOAD = [&](int st, int k0) {
        float* As = sm + (st % RST) * (2 * STG_F);
        float* Bs = As + STG_F;
        #pragma unroll
        for (int i = 0; i < 4; i++) {
            int r = lr + i * 32;
            cpa16(&As[r * SPITCH + lc], Ab + (size_t)r * ldk + k0 + lc);
            cpa16(&Bs[r * SPITCH + lc], Bb + (size_t)r * ldk + k0 + lc);
        }
    };

    const int NS = kchunk / 16;
    LOAD(0, 0);  CP_COMMIT();
    LOAD(1, 16); CP_COMMIT();

    for (int s = 0; s < NS; s++) {
        if (s == NS - 1) { CP_WAIT0(); } else { CP_WAIT1(); }
        __syncthreads();
        if (s + 2 < NS) { LOAD(s + 2, (s + 2) * 16); CP_COMMIT(); }

        const float* As = sm + (s % RST) * (2 * STG_F);
        const float* Bs = As + STG_F;

        unsigned a0[4][4], a1[4][4], b0[8][2], b1[8][2];

        // A-frags ks=0 (kk=0)
        #pragma unroll
        for (int im = 0; im < 4; im++) {
            int m = wm + im * 16;
            a0[im][0] = fu(As[(m + g    ) * SPITCH + tg    ]);
            a0[im][1] = fu(As[(m + g + 8) * SPITCH + tg    ]);
            a0[im][2] = fu(As[(m + g    ) * SPITCH + tg + 4]);
            a0[im][3] = fu(As[(m + g + 8) * SPITCH + tg + 4]);
        }
        // first two B columns of ks=0
        #pragma unroll
        for (int jn = 0; jn < 2; jn++) {
            int n = wn + jn * 8;
            b0[jn][0] = fu(Bs[(n + g) * SPITCH + tg    ]);
            b0[jn][1] = fu(Bs[(n + g) * SPITCH + tg + 4]);
        }

        // ks=0: per-jn pipeline; fetch ks=1 A-frags during last two groups
        #pragma unroll
        for (int jn = 0; jn < 8; jn++) {
            if (jn < 6) {
                int n = wn + (jn + 2) * 8;
                b0[jn + 2][0] = fu(Bs[(n + g) * SPITCH + tg    ]);
                b0[jn + 2][1] = fu(Bs[(n + g) * SPITCH + tg + 4]);
            } else {
                #pragma unroll
                for (int h = 0; h < 2; h++) {
                    int im = (jn - 6) * 2 + h;
                    int m = wm + im * 16;
                    a1[im][0] = fu(As[(m + g    ) * SPITCH + 8 + tg    ]);
                    a1[im][1] = fu(As[(m + g + 8) * SPITCH + 8 + tg    ]);
                    a1[im][2] = fu(As[(m + g    ) * SPITCH + 8 + tg + 4]);
                    a1[im][3] = fu(As[(m + g + 8) * SPITCH + 8 + tg + 4]);
                }
            }
            #pragma unroll
            for (int im = 0; im < 4; im++)
                mma8(acc[im][jn], a0[im][0], a0[im][1], a0[im][2], a0[im][3],
                     b0[jn][0], b0[jn][1]);
        }

        // first two B columns of ks=1
        #pragma unroll
        for (int jn = 0; jn < 2; jn++) {
            int n = wn + jn * 8;
            b1[jn][0] = fu(Bs[(n + g) * SPITCH + 8 + tg    ]);
            b1[jn][1] = fu(Bs[(n + g) * SPITCH + 8 + tg + 4]);
        }
        // ks=1: per-jn pipeline
        #pragma unroll
        for (int jn = 0; jn < 8; jn++) {
            if (jn < 6) {
                int n = wn + (jn + 2) * 8;
                b1[jn + 2][0] = fu(Bs[(n + g) * SPITCH + 8 + tg    ]);
                b1[jn + 2][1] = fu(Bs[(n + g) * SPITCH + 8 + tg + 4]);
            }
            #pragma unroll
            for (int im = 0; im < 4; im++)
                mma8(acc[im][jn], a1[im][0], a1[im][1], a1[im][2], a1[im][3],
                     b1[jn][0], b1[jn][1]);
        }
    }

    float* Cz = C + (size_t)blockIdx.z * czstride;
    #pragma unroll
    for (int im = 0; im < 4; im++) {
        int m = m0 + wm + im * 16 + g;
        #pragma unroll
        for (int jn = 0; jn < 8; jn++) {
            int n = n0 + wn + jn * 8 + tg * 2;
            *(float2*)(Cz + (size_t)m * D + n)       = make_float2(acc[im][jn][0], acc[im][jn][1]);
            *(float2*)(Cz + (size_t)(m + 8) * D + n) = make_float2(acc[im][jn][2], acc[im][jn][3]);
        }
    }
}

// ============================================================================
// G = x^T x, MN-major loads (no transpose): partial[z][m][n] = sum_k x[k][m]x[k][n]
// Same per-jn software pipeline; blockIdx.x = lower-triangle tile pair (36).
// ============================================================================
#define GPITCH 136
#define GSTG_F (16 * GPITCH)             // 2176 floats per tile buffer
#define GSMEM_DYN (RST * 2 * GSTG_F * 4) // 52224 bytes

__global__ __launch_bounds__(128, 2)
void gemm_g(const float* __restrict__ X) {
    extern __shared__ float sm[];

    const int tid  = threadIdx.x;
    const int warp = tid >> 5, lane = tid & 31;
    const int g = lane >> 2, tg = lane & 3;
    const int wm = (warp >> 1) * 64;
    const int wn = (warp & 1) * 64;

    int t = blockIdx.x;
    int bi = 0;
    while ((bi + 1) * (bi + 2) / 2 <= t) bi++;
    int bj = t - bi * (bi + 1) / 2;
    const int m0 = bi * 128, n0 = bj * 128;
    const int kbase = blockIdx.z * (BATCH / GSPLIT);   // 2048 per split

    float acc[4][8][4];
    #pragma unroll
    for (int i = 0; i < 4; i++)
        #pragma unroll
        for (int j = 0; j < 8; j++)
            #pragma unroll
            for (int q = 0; q < 4; q++) acc[i][j][q] = 0.f;

    const int lr = tid >> 3;          // 0..15 (k row)
    const int lc = (tid & 7) << 2;    // 0..28

    auto LOAD = [&](int st, int k0) {
        float* As = sm + (st % RST) * (2 * GSTG_F);
        float* Bs = As + GSTG_F;
        const float* xr = X + (size_t)(kbase + k0 + lr) * D;
        #pragma unroll
        for (int i = 0; i < 4; i++) {
            int c = lc + 32 * i;
            cpa16(&As[lr * GPITCH + c], xr + m0 + c);
            cpa16(&Bs[lr * GPITCH + c], xr + n0 + c);
        }
    };

    const int NS = (BATCH / GSPLIT) / 16;  // 128
    LOAD(0, 0);  CP_COMMIT();
    LOAD(1, 16); CP_COMMIT();

    for (int s = 0; s < NS; s++) {
        if (s == NS - 1) { CP_WAIT0(); } else { CP_WAIT1(); }
        __syncthreads();
        if (s + 2 < NS) { LOAD(s + 2, (s + 2) * 16); CP_COMMIT(); }

        const float* As = sm + (s % RST) * (2 * GSTG_F);
        const float* Bs = As + GSTG_F;

        unsigned a0[4][4], a1[4][4], b0[8][2], b1[8][2];

        #pragma unroll
        for (int im = 0; im < 4; im++) {
            int m = wm + im * 16;
            a0[im][0] = fu(As[(tg    ) * GPITCH + m + g    ]);
            a0[im][1] = fu(As[(tg    ) * GPITCH + m + g + 8]);
            a0[im][2] = fu(As[(tg + 4) * GPITCH + m + g    ]);
            a0[im][3] = fu(As[(tg + 4) * GPITCH + m + g + 8]);
        }
        #pragma unroll
        for (int jn = 0; jn < 2; jn++) {
            int n = wn + jn * 8;
            b0[jn][0] = fu(Bs[(tg    ) * GPITCH + n + g]);
            b0[jn][1] = fu(Bs[(tg + 4) * GPITCH + n + g]);
        }

        #pragma unroll
        for (int jn = 0; jn < 8; jn++) {
            if (jn < 6) {
                int n = wn + (jn + 2) * 8;
                b0[jn + 2][0] = fu(Bs[(tg    ) * GPITCH + n + g]);
                b0[jn + 2][1] = fu(Bs[(tg + 4) * GPITCH + n + g]);
            } else {
                #pragma unroll
                for (int h = 0; h < 2; h++) {
                    int im = (jn - 6) * 2 + h;
                    int m = wm + im * 16;
                    a1[im][0] = fu(As[(8 + tg    ) * GPITCH + m + g    ]);
                    a1[im][1] = fu(As[(8 + tg    ) * GPITCH + m + g + 8]);
                    a1[im][2] = fu(As[(8 + tg + 4) * GPITCH + m + g    ]);
                    a1[im][3] = fu(As[(8 + tg + 4) * GPITCH + m + g + 8]);
                }
            }
            #pragma unroll
            for (int im = 0; im < 4; im++)
                mma8(acc[im][jn], a0[im][0], a0[im][1], a0[im][2], a0[im][3],
                     b0[jn][0], b0[jn][1]);
        }

        #pragma unroll
        for (int jn = 0; jn < 2; jn++) {
            int n = wn + jn * 8;
            b1[jn][0] = fu(Bs[(8 + tg    ) * GPITCH + n + g]);
            b1[jn][1] = fu(Bs[(8 + tg + 4) * GPITCH + n + g]);
        }
        #pragma unroll
        for (int jn = 0; jn < 8; jn++) {
            if (jn < 6) {
                int n = wn + (jn + 2) * 8;
                b1[jn + 2][0] = fu(Bs[(8 + tg    ) * GPITCH + n + g]);
                b1[jn + 2][1] = fu(Bs[(8 + tg + 4) * GPITCH + n + g]);
            }
            #pragma unroll
            for (int im = 0; im < 4; im++)
                mma8(acc[im][jn], a1[im][0], a1[im][1], a1[im][2], a1[im][3],
                     b1[jn][0], b1[jn][1]);
        }
    }

    float* Cp = (float*)g_part + (size_t)blockIdx.z * D * D;
    #pragma unroll
    for (int im = 0; im < 4; im++) {
        int m = m0 + wm + im * 16 + g;
        #pragma unroll
        for (int jn = 0; jn < 8; jn++) {
            int n = n0 + wn + jn * 8 + tg * 2;
            *(float2*)(Cp + (size_t)m * D + n)       = make_float2(acc[im][jn][0], acc[im][jn][1]);
            *(float2*)(Cp + (size_t)(m + 8) * D + n) = make_float2(acc[im][jn][2], acc[im][jn][3]);
        }
    }
}

// ============================================================================
// Reduce G split-K partials with symmetry mirror; round to tf32.
// ============================================================================
__global__ void greduce_kernel() {
    int i = blockIdx.x * 256 + threadIdx.x;        // grid 4096 -> 1M elements
    int r = i >> 10, c = i & 1023;
    size_t src = ((r >> 7) >= (c >> 7)) ? ((size_t)r * D + c) : ((size_t)c * D + r);
    float s = 0.f;
    #pragma unroll
    for (int z = 0; z < GSPLIT; z++) s += g_part[(size_t)z * D * D + src];
    g_G[i] = __uint_as_float(tf32u(s));
}

// ============================================================================
// mean(fast^2, axis=0): two deterministic stages
// ============================================================================
__global__ void msq_stageA() {
    int c  = blockIdx.x * 256 + threadIdx.x;     // grid.x = 4
    int r0 = blockIdx.y * 256;                   // grid.y = 64
    float s0 = 0.f, s1 = 0.f, s2 = 0.f, s3 = 0.f;
    const float* fp = (const float*)g_fast + (size_t)r0 * D + c;
    #pragma unroll 4
    for (int j = 0; j < 256; j += 4) {
        float v0 = fp[(size_t)(j + 0) * D];
        float v1 = fp[(size_t)(j + 1) * D];
        float v2 = fp[(size_t)(j + 2) * D];
        float v3 = fp[(size_t)(j + 3) * D];
        s0 += v0 * v0; s1 += v1 * v1; s2 += v2 * v2; s3 += v3 * v3;
    }
    g_msq_part[blockIdx.y * D + c] = (s0 + s1) + (s2 + s3);
}

__global__ void msq_stageB() {
    int c = blockIdx.x * 256 + threadIdx.x;      // grid.x = 4
    float s = 0.f;
    #pragma unroll
    for (int j = 0; j < 64; j++) s += g_msq_part[j * D + c];
    g_msq[c] = s * (1.0f / (float)BATCH);
}

// ============================================================================
// eff_lr = mean(plasticity) * 0.1
// ============================================================================
__global__ void efflr_kernel(const float* __restrict__ p) {
    int t = threadIdx.x;
    float s = 0.f;
    for (int j = t; j < BATCH; j += 256) s += p[j];
    s = warpSum(s);
    __shared__ float sh[8];
    if ((t & 31) == 0) sh[t >> 5] = s;
    __syncthreads();
    if (t == 0) {
        float tot = 0.f;
        #pragma unroll
        for (int i = 0; i < 8; i++) tot += sh[i];
        g_efflr[0] = tot * (0.1f / (float)BATCH);
    }
}

// ============================================================================
// W_fast_new = W_fast + tanh(hebb/B - msq[o]*W_fast) * eff_lr
// ============================================================================
__global__ __launch_bounds__(256)
void finalize_w(const float* __restrict__ Wf, float* __restrict__ wnew) {
    int o = blockIdx.x;
    float msq = g_msq[o];
    float lr  = g_efflr[0];
    for (int j = threadIdx.x; j < D; j += 256) {
        size_t i = (size_t)o * D + j;
        float h = 0.f;
        #pragma unroll
        for (int z = 0; z < HSPLIT; z++) h += g_part[(size_t)z * D * D + i];
        float wf = Wf[i];
        wnew[i] = wf + tanhf(h * (1.0f / (float)BATCH) - msq * wf) * lr;
    }
}

// ============================================================================
// LayerNorm over combined = slow + alpha*fast; one block per row
// ============================================================================
__global__ __launch_bounds__(256)
void ln_kernel(const float* __restrict__ slow, const float* __restrict__ alpha,
               const float* __restrict__ gamma, const float* __restrict__ beta,
               float* __restrict__ out) {
    int r = blockIdx.x, t = threadIdx.x;
    const float a = alpha[0];
    float4 s4 = ((const float4*)(slow + (size_t)r * D))[t];
    float4 f4 = ((const float4*)((const float*)g_fast + (size_t)r * D))[t];
    float4 v;
    v.x = s4.x + a * f4.x; v.y = s4.y + a * f4.y;
    v.z = s4.z + a * f4.z; v.w = s4.w + a * f4.w;

    float sum = (v.x + v.y) + (v.z + v.w);
    float sq  = (v.x * v.x + v.y * v.y) + (v.z * v.z + v.w * v.w);
    sum = warpSum(sum); sq = warpSum(sq);

    __shared__ float sh[16];
    int w = t >> 5, l = t & 31;
    if (l == 0) { sh[w] = sum; sh[8 + w] = sq; }
    __syncthreads();
    if (t == 0) {
        float s = 0.f, q = 0.f;
        #pragma unroll
        for (int i = 0; i < 8; i++) { s += sh[i]; q += sh[8 + i]; }
        sh[0] = s; sh[8] = q;
    }
    __syncthreads();
    float mu  = sh[0] * (1.0f / (float)D);
    float var = sh[8] * (1.0f / (float)D) - mu * mu;
    float rs  = rsqrtf(var + LN_EPS);

    float4 g4 = ((const float4*)gamma)[t];
    float4 b4 = ((const float4*)beta)[t];
    float4 o4;
    o4.x = (v.x - mu) * rs * g4.x + b4.x;
    o4.y = (v.y - mu) * rs * g4.y + b4.y;
    o4.z = (v.z - mu) * rs * g4.z + b4.z;
    o4.w = (v.w - mu) * rs * g4.w + b4.w;
    ((float4*)(out + (size_t)r * D))[t] = o4;
}

// ============================================================================
extern "C" void kernel_launch(void* const* d_in, const int* in_sizes, int n_in,
                              void* d_out, int out_size) {
    (void)in_sizes; (void)n_in; (void)out_size;
    const float* x     = (const float*)d_in[0];
    const float* plast = (const float*)d_in[1];
    const float* alpha = (const float*)d_in[2];
    const float* Wslow = (const float*)d_in[3];
    const float* Wfast = (const float*)d_in[4];
    const float* gamma = (const float*)d_in[5];
    const float* beta  = (const float*)d_in[6];

    float* out  = (float*)d_out;                 // [16384, 1024]
    float* slow = out  + (size_t)BATCH * D;      // [16384, 1024]
    float* wnew = slow + (size_t)BATCH * D;      // [1024, 1024]

    float* d_xc   = nullptr; cudaGetSymbolAddress((void**)&d_xc,   g_xc);
    float* d_wsc  = nullptr; cudaGetSymbolAddress((void**)&d_wsc,  g_wsc);
    float* d_wfc  = nullptr; cudaGetSymbolAddress((void**)&d_wfc,  g_wfc);
    float* d_fast = nullptr; cudaGetSymbolAddress((void**)&d_fast, g_fast);
    float* d_part = nullptr; cudaGetSymbolAddress((void**)&d_part, g_part);
    float* d_G    = nullptr; cudaGetSymbolAddress((void**)&d_G,    g_G);

    static bool attr_set = false;
    if (!attr_set) {
        cudaFuncSetAttribute(gemm_mma, cudaFuncAttributeMaxDynamicSharedMemorySize, SMEM_DYN);
        cudaFuncSetAttribute(gemm_g,   cudaFuncAttributeMaxDynamicSharedMemorySize, GSMEM_DYN);
        attr_set = true;
    }

    cvt_rna_kernel<<<1024, 256>>>((const float4*)x,     (float4*)d_xc,  BATCH * D / 4);
    cvt_rna_kernel<<<256,  256>>>((const float4*)Wslow, (float4*)d_wsc, D * D / 4);
    cvt_rna_kernel<<<256,  256>>>((const float4*)Wfast, (float4*)d_wfc, D * D / 4);

    // slow = x @ Wslow^T ; fast = x @ Wfast^T   (grid: n-tiles x m-tiles)
    gemm_mma<<<dim3(8, 128), 128, SMEM_DYN>>>(d_xc, d_wsc, slow,   D, D, 0);
    gemm_mma<<<dim3(8, 128), 128, SMEM_DYN>>>(d_xc, d_wfc, d_fast, D, D, 0);

    msq_stageA<<<dim3(4, 64), 256>>>();
    msq_stageB<<<4, 256>>>();
    efflr_kernel<<<1, 256>>>(plast);

    // G = x^T x : lower-triangle tiles only (36 pairs), split-K over batch
    gemm_g<<<dim3(36, 1, GSPLIT), 128, GSMEM_DYN>>>(d_xc);
    greduce_kernel<<<4096, 256>>>();

    // hebb = Wf @ G (G symmetric -> B rows are G rows), split-K 4 into g_part
    gemm_mma<<<dim3(8, 8, HSPLIT), 128, SMEM_DYN>>>(d_wfc, d_G, d_part,
                                                    D, D / HSPLIT,
                                                    (long long)D * D);

    finalize_w<<<1024, 256>>>(Wfast, wnew);
    ln_kernel<<<16384, 256>>>(slow, alpha, gamma, beta, out);
}

// round 14
// speedup vs baseline: 1.9970x; 1.9970x over previous
#include <cuda_runtime.h>
#include <cuda_fp16.h>
#include <cstdint>

#define BATCH 16384
#define D     1024
#define LN_EPS 1e-5f
#define GSPLIT 8          // split-K for G = x^T x
#define HSPLIT 4          // split-K for hebb = Wf * G

// ---------------- scratch (static device globals; no runtime alloc) ----------
__device__ __align__(16) __half g_xh [(size_t)BATCH * D];     // x in fp16
__device__ __align__(16) __half g_wsh[(size_t)D * D];         // W_slow fp16
__device__ __align__(16) __half g_wfh[(size_t)D * D];         // W_fast fp16
__device__ __align__(16) __half g_Gh [(size_t)D * D];         // G = x^T x, fp16
__device__ __align__(16) float  g_fast[(size_t)BATCH * D];    // fast, fp32
__device__ __align__(16) float  g_part[(size_t)GSPLIT * D * D]; // split-K partials
__device__ float g_msq_part[64 * D];
__device__ float g_msq[D];
__device__ float g_efflr[1];

// ---------------- helpers ----------------------------------------------------
__device__ __forceinline__ void mma16(float c[4], const unsigned a[4],
                                      unsigned b0, unsigned b1) {
    asm volatile(
        "mma.sync.aligned.m16n8k16.row.col.f32.f16.f16.f32 "
        "{%0,%1,%2,%3}, {%4,%5,%6,%7}, {%8,%9}, {%0,%1,%2,%3};\n"
        : "+f"(c[0]), "+f"(c[1]), "+f"(c[2]), "+f"(c[3])
        : "r"(a[0]), "r"(a[1]), "r"(a[2]), "r"(a[3]), "r"(b0), "r"(b1));
}

#define LDSM4(r0,r1,r2,r3,addr) \
    asm volatile("ldmatrix.sync.aligned.m8n8.x4.shared.b16 {%0,%1,%2,%3}, [%4];" \
                 : "=r"(r0),"=r"(r1),"=r"(r2),"=r"(r3) : "r"(addr))
#define LDSM4T(r0,r1,r2,r3,addr) \
    asm volatile("ldmatrix.sync.aligned.m8n8.x4.trans.shared.b16 {%0,%1,%2,%3}, [%4];" \
                 : "=r"(r0),"=r"(r1),"=r"(r2),"=r"(r3) : "r"(addr))

__device__ __forceinline__ void cpa16_s(unsigned sdst, const void* src) {
    asm volatile("cp.async.cg.shared.global [%0], [%1], 16;\n" :: "r"(sdst), "l"(src));
}
#define CP_COMMIT() asm volatile("cp.async.commit_group;\n" ::: "memory")
#define CP_WAIT0()  asm volatile("cp.async.wait_group 0;\n" ::: "memory")
#define CP_WAIT1()  asm volatile("cp.async.wait_group 1;\n" ::: "memory")

__device__ __forceinline__ float warpSum(float v) {
    #pragma unroll
    for (int o = 16; o > 0; o >>= 1) v += __shfl_xor_sync(0xffffffffu, v, o);
    return v;
}

// smem swizzles (16B chunk c within row r), verified conflict-free per LDSM phase
__device__ __forceinline__ unsigned off64(int r, int c) {       // 64B-pitch rows
    return (unsigned)(r * 64 + ((c ^ ((r >> 1) & 3)) << 4));
}
__device__ __forceinline__ unsigned off256(int r, int c) {      // 256B-pitch rows
    return (unsigned)(r * 256 + (((c & 8) | ((c ^ r) & 7)) << 4));
}

// ============================================================================
// Pre-convert: fp32 -> fp16 (rn)
// ============================================================================
__global__ void cvt_h_kernel(const float2* __restrict__ s, __half2* __restrict__ d, int n2) {
    int i  = blockIdx.x * 256 + threadIdx.x;
    int st = gridDim.x * 256;
    for (; i < n2; i += st) {
        float2 v = s[i];
        d[i] = __floats2half2_rn(v.x, v.y);
    }
}

// ============================================================================
// fp16 TN GEMM: C[m][n] = sum_k A[m][k] * B[n][k], fp32 accum.
// 128x128 CTA tile, 4 warps (2x2 of 64x64), BK=32, 3-stage cp.async ring,
// ldmatrix.x4 fragment loads, m16n8k16 HMMA.
// blockIdx.z = split-K chunk; kbase folded into Ab/Bb; C += z*czstride.
// ============================================================================
#define HSTAGE_A 8192               // 128 rows * 64B
#define HSTAGE   (2 * HSTAGE_A)     // 16 KB (A + B)
#define HSMEM    (3 * HSTAGE)       // 48 KB

__global__ __launch_bounds__(128, 2)
void gemm_h(const __half* __restrict__ A, const __half* __restrict__ B,
            float* __restrict__ C, int ldk, int kchunk, long long czstride) {
    extern __shared__ char dynsm[];
    unsigned dbase = (unsigned)__cvta_generic_to_shared(dynsm);

    const int tid  = threadIdx.x;
    const int warp = tid >> 5, lane = tid & 31;
    const int g = lane >> 2, tg = lane & 3;
    const int wm = (warp >> 1) * 64, wn = (warp & 1) * 64;
    const int m0 = blockIdx.y * 128, n0 = blockIdx.x * 128;
    const int kbase = blockIdx.z * kchunk;

    const __half* __restrict__ Ab = A + (size_t)m0 * ldk + kbase;
    const __half* __restrict__ Bb = B + (size_t)n0 * ldk + kbase;

    float acc[4][8][4];
    #pragma unroll
    for (int i = 0; i < 4; i++)
        #pragma unroll
        for (int j = 0; j < 8; j++)
            #pragma unroll
            for (int q = 0; q < 4; q++) acc[i][j][q] = 0.f;

    // Precomputed per-lane ldmatrix addresses (relative to stage base).
    const int q = lane >> 3, rr = lane & 7;
    unsigned aoff[2][4], boff[2][4];
    #pragma unroll
    for (int ks = 0; ks < 2; ks++) {
        #pragma unroll
        for (int im = 0; im < 4; im++) {
            int r = wm + im * 16 + (q & 1) * 8 + rr;     // a0/a1: m rows; a2/a3: k+8
            aoff[ks][im] = off64(r, ks * 2 + (q >> 1));
        }
        #pragma unroll
        for (int p = 0; p < 4; p++) {                     // pair p covers jn=2p,2p+1
            int r = wn + p * 16 + (q >> 1) * 8 + rr;
            boff[ks][p] = HSTAGE_A + off64(r, ks * 2 + (q & 1));
        }
    }

    auto LOAD = [&](int st, int k0) {
        unsigned sa = dbase + (unsigned)(st % 3) * HSTAGE;
        #pragma unroll
        for (int i = 0; i < 4; i++) {
            int idx = tid + i * 128;
            int r = idx >> 2, c = idx & 3;
            cpa16_s(sa + off64(r, c),            Ab + (size_t)r * ldk + k0 + c * 8);
            cpa16_s(sa + HSTAGE_A + off64(r, c), Bb + (size_t)r * ldk + k0 + c * 8);
        }
    };

    const int NS = kchunk / 32;
    LOAD(0, 0);  CP_COMMIT();
    LOAD(1, 32); CP_COMMIT();

    for (int s = 0; s < NS; s++) {
        if (s == NS - 1) { CP_WAIT0(); } else { CP_WAIT1(); }
        __syncthreads();
        if (s + 2 < NS) { LOAD(s + 2, (s + 2) * 32); CP_COMMIT(); }

        unsigned sbase = dbase + (unsigned)(s % 3) * HSTAGE;
        #pragma unroll
        for (int ks = 0; ks < 2; ks++) {
            unsigned a[4][4], b[4][4];
            #pragma unroll
            for (int im = 0; im < 4; im++)
                LDSM4(a[im][0], a[im][1], a[im][2], a[im][3], sbase + aoff[ks][im]);
            #pragma unroll
            for (int p = 0; p < 4; p++)
                LDSM4(b[p][0], b[p][1], b[p][2], b[p][3], sbase + boff[ks][p]);
            #pragma unroll
            for (int im = 0; im < 4; im++)
                #pragma unroll
                for (int jn = 0; jn < 8; jn++)
                    mma16(acc[im][jn], a[im], b[jn >> 1][(jn & 1) * 2],
                          b[jn >> 1][(jn & 1) * 2 + 1]);
        }
    }

    float* Cz = C + (size_t)blockIdx.z * czstride;
    #pragma unroll
    for (int im = 0; im < 4; im++) {
        int m = m0 + wm + im * 16 + g;
        #pragma unroll
        for (int jn = 0; jn < 8; jn++) {
            int n = n0 + wn + jn * 8 + tg * 2;
            *(float2*)(Cz + (size_t)m * D + n)       = make_float2(acc[im][jn][0], acc[im][jn][1]);
            *(float2*)(Cz + (size_t)(m + 8) * D + n) = make_float2(acc[im][jn][2], acc[im][jn][3]);
        }
    }
}

// ============================================================================
// G = x^T x (fp16, ldmatrix.trans on natural [k][m] layout, no transpose).
// partial[z][m][n] = sum_{k chunk z} x[k][m] * x[k][n]
// BK=32 (32 k-rows x 256B per tile), 3-stage ring.
// blockIdx.x = lower-triangle tile pair (36); blockIdx.z = split (8).
// ============================================================================
#define GSTAGE_A 8192               // 32 rows * 256B
#define GSTAGE   (2 * GSTAGE_A)     // 16 KB
#define GSMEM    (3 * GSTAGE)       // 48 KB

__global__ __launch_bounds__(128, 2)
void gemm_gh(const __half* __restrict__ X) {
    extern __shared__ char dynsm[];
    unsigned dbase = (unsigned)__cvta_generic_to_shared(dynsm);

    const int tid  = threadIdx.x;
    const int warp = tid >> 5, lane = tid & 31;
    const int g = lane >> 2, tg = lane & 3;
    const int wm = (warp >> 1) * 64, wn = (warp & 1) * 64;

    int t = blockIdx.x;
    int bi = 0;
    while ((bi + 1) * (bi + 2) / 2 <= t) bi++;
    int bj = t - bi * (bi + 1) / 2;
    const int m0 = bi * 128, n0 = bj * 128;
    const int kbase = blockIdx.z * (BATCH / GSPLIT);   // 2048 per split

    float acc[4][8][4];
    #pragma unroll
    for (int i = 0; i < 4; i++)
        #pragma unroll
        for (int j = 0; j < 8; j++)
            #pragma unroll
            for (int q = 0; q < 4; q++) acc[i][j][q] = 0.f;

    const int q = lane >> 3, rr = lane & 7;
    unsigned aoff[2][4], boff[2][4];
    #pragma unroll
    for (int ks = 0; ks < 2; ks++) {
        #pragma unroll
        for (int im = 0; im < 4; im++) {
            int r = ks * 16 + (q >> 1) * 8 + rr;           // stored row = k
            int c = wm / 8 + im * 2 + (q & 1);             // stored chunk = m/8
            aoff[ks][im] = off256(r, c);
        }
        #pragma unroll
        for (int p = 0; p < 4; p++) {
            int r = ks * 16 + (q & 1) * 8 + rr;
            int c = wn / 8 + p * 2 + (q >> 1);
            boff[ks][p] = GSTAGE_A + off256(r, c);
        }
    }

    auto LOAD = [&](int st, int k0) {
        unsigned sa = dbase + (unsigned)(st % 3) * GSTAGE;
        const __half* xr = X + (size_t)(kbase + k0) * D;
        #pragma unroll
        for (int i = 0; i < 4; i++) {
            int idx = tid + i * 128;
            int r = idx >> 4, c = idx & 15;
            cpa16_s(sa + off256(r, c),            xr + (size_t)r * D + m0 + c * 8);
            cpa16_s(sa + GSTAGE_A + off256(r, c), xr + (size_t)r * D + n0 + c * 8);
        }
    };

    const int NS = (BATCH / GSPLIT) / 32;  // 64
    LOAD(0, 0);  CP_COMMIT();
    LOAD(1, 32); CP_COMMIT();

    for (int s = 0; s < NS; s++) {
        if (s == NS - 1) { CP_WAIT0(); } else { CP_WAIT1(); }
        __syncthreads();
        if (s + 2 < NS) { LOAD(s + 2, (s + 2) * 32); CP_COMMIT(); }

        unsigned sbase = dbase + (unsigned)(s % 3) * GSTAGE;
        #pragma unroll
        for (int ks = 0; ks < 2; ks++) {
            unsigned a[4][4], b[4][4];
            #pragma unroll
            for (int im = 0; im < 4; im++)
                LDSM4T(a[im][0], a[im][1], a[im][2], a[im][3], sbase + aoff[ks][im]);
            #pragma unroll
            for (int p = 0; p < 4; p++)
                LDSM4T(b[p][0], b[p][1], b[p][2], b[p][3], sbase + boff[ks][p]);
            #pragma unroll
            for (int im = 0; im < 4; im++)
                #pragma unroll
                for (int jn = 0; jn < 8; jn++)
                    mma16(acc[im][jn], a[im], b[jn >> 1][(jn & 1) * 2],
                          b[jn >> 1][(jn & 1) * 2 + 1]);
        }
    }

    float* Cp = (float*)g_part + (size_t)blockIdx.z * D * D;
    #pragma unroll
    for (int im = 0; im < 4; im++) {
        int m = m0 + wm + im * 16 + g;
        #pragma unroll
        for (int jn = 0; jn < 8; jn++) {
            int n = n0 + wn + jn * 8 + tg * 2;
            *(float2*)(Cp + (size_t)m * D + n)       = make_float2(acc[im][jn][0], acc[im][jn][1]);
            *(float2*)(Cp + (size_t)(m + 8) * D + n) = make_float2(acc[im][jn][2], acc[im][jn][3]);
        }
    }
}

// ============================================================================
// Reduce G split-K partials with symmetry mirror; round to fp16.
// ============================================================================
__global__ void greduce_kernel() {
    int i = blockIdx.x * 256 + threadIdx.x;        // grid 4096 -> 1M elements
    int r = i >> 10, c = i & 1023;
    size_t src = ((r >> 7) >= (c >> 7)) ? ((size_t)r * D + c) : ((size_t)c * D + r);
    float s = 0.f;
    #pragma unroll
    for (int z = 0; z < GSPLIT; z++) s += g_part[(size_t)z * D * D + src];
    g_Gh[i] = __float2half_rn(s);
}

// ============================================================================
// mean(fast^2, axis=0): two deterministic stages
// ============================================================================
__global__ void msq_stageA() {
    int c  = blockIdx.x * 256 + threadIdx.x;     // grid.x = 4
    int r0 = blockIdx.y * 256;                   // grid.y = 64
    float s0 = 0.f, s1 = 0.f, s2 = 0.f, s3 = 0.f;
    const float* fp = (const float*)g_fast + (size_t)r0 * D + c;
    #pragma unroll 4
    for (int j = 0; j < 256; j += 4) {
        float v0 = fp[(size_t)(j + 0) * D];
        float v1 = fp[(size_t)(j + 1) * D];
        float v2 = fp[(size_t)(j + 2) * D];
        float v3 = fp[(size_t)(j + 3) * D];
        s0 += v0 * v0; s1 += v1 * v1; s2 += v2 * v2; s3 += v3 * v3;
    }
    g_msq_part[blockIdx.y * D + c] = (s0 + s1) + (s2 + s3);
}

__global__ void msq_stageB() {
    int c = blockIdx.x * 256 + threadIdx.x;      // grid.x = 4
    float s = 0.f;
    #pragma unroll
    for (int j = 0; j < 64; j++) s += g_msq_part[j * D + c];
    g_msq[c] = s * (1.0f / (float)BATCH);
}

// ============================================================================
// eff_lr = mean(plasticity) * 0.1
// ============================================================================
__global__ void efflr_kernel(const float* __restrict__ p) {
    int t = threadIdx.x;
    float s = 0.f;
    for (int j = t; j < BATCH; j += 256) s += p[j];
    s = warpSum(s);
    __shared__ float sh[8];
    if ((t & 31) == 0) sh[t >> 5] = s;
    __syncthreads();
    if (t == 0) {
        float tot = 0.f;
        #pragma unroll
        for (int i = 0; i < 8; i++) tot += sh[i];
        g_efflr[0] = tot * (0.1f / (float)BATCH);
    }
}

// ============================================================================
// W_fast_new = W_fast + tanh(hebb/B - msq[o]*W_fast) * eff_lr
// ============================================================================
__global__ __launch_bounds__(256)
void finalize_w(const float* __restrict__ Wf, float* __restrict__ wnew) {
    int o = blockIdx.x;
    float msq = g_msq[o];
    float lr  = g_efflr[0];
    for (int j = threadIdx.x; j < D; j += 256) {
        size_t i = (size_t)o * D + j;
        float h = 0.f;
        #pragma unroll
        for (int z = 0; z < HSPLIT; z++) h += g_part[(size_t)z * D * D + i];
        float wf = Wf[i];
        wnew[i] = wf + tanhf(h * (1.0f / (float)BATCH) - msq * wf) * lr;
    }
}

// ============================================================================
// LayerNorm over combined = slow + alpha*fast; one block per row
// ============================================================================
__global__ __launch_bounds__(256)
void ln_kernel(const float* __restrict__ slow, const float* __restrict__ alpha,
               const float* __restrict__ gamma, const float* __restrict__ beta,
               float* __restrict__ out) {
    int r = blockIdx.x, t = threadIdx.x;
    const float a = alpha[0];
    float4 s4 = ((const float4*)(slow + (size_t)r * D))[t];
    float4 f4 = ((const float4*)((const float*)g_fast + (size_t)r * D))[t];
    float4 v;
    v.x = s4.x + a * f4.x; v.y = s4.y + a * f4.y;
    v.z = s4.z + a * f4.z; v.w = s4.w + a * f4.w;

    float sum = (v.x + v.y) + (v.z + v.w);
    float sq  = (v.x * v.x + v.y * v.y) + (v.z * v.z + v.w * v.w);
    sum = warpSum(sum); sq = warpSum(sq);

    __shared__ float sh[16];
    int w = t >> 5, l = t & 31;
    if (l == 0) { sh[w] = sum; sh[8 + w] = sq; }
    __syncthreads();
    if (t == 0) {
        float s = 0.f, qq = 0.f;
        #pragma unroll
        for (int i = 0; i < 8; i++) { s += sh[i]; qq += sh[8 + i]; }
        sh[0] = s; sh[8] = qq;
    }
    __syncthreads();
    float mu  = sh[0] * (1.0f / (float)D);
    float var = sh[8] * (1.0f / (float)D) - mu * mu;
    float rs  = rsqrtf(var + LN_EPS);

    float4 g4 = ((const float4*)gamma)[t];
    float4 b4 = ((const float4*)beta)[t];
    float4 o4;
    o4.x = (v.x - mu) * rs * g4.x + b4.x;
    o4.y = (v.y - mu) * rs * g4.y + b4.y;
    o4.z = (v.z - mu) * rs * g4.z + b4.z;
    o4.w = (v.w - mu) * rs * g4.w + b4.w;
    ((float4*)(out + (size_t)r * D))[t] = o4;
}

// ============================================================================
extern "C" void kernel_launch(void* const* d_in, const int* in_sizes, int n_in,
                              void* d_out, int out_size) {
    (void)in_sizes; (void)n_in; (void)out_size;
    const float* x     = (const float*)d_in[0];
    const float* plast = (const float*)d_in[1];
    const float* alpha = (const float*)d_in[2];
    const float* Wslow = (const float*)d_in[3];
    const float* Wfast = (const float*)d_in[4];
    const float* gamma = (const float*)d_in[5];
    const float* beta  = (const float*)d_in[6];

    float* out  = (float*)d_out;                 // [16384, 1024]
    float* slow = out  + (size_t)BATCH * D;      // [16384, 1024]
    float* wnew = slow + (size_t)BATCH * D;      // [1024, 1024]

    __half* d_xh  = nullptr; cudaGetSymbolAddress((void**)&d_xh,  g_xh);
    __half* d_wsh = nullptr; cudaGetSymbolAddress((void**)&d_wsh, g_wsh);
    __half* d_wfh = nullptr; cudaGetSymbolAddress((void**)&d_wfh, g_wfh);
    __half* d_Gh  = nullptr; cudaGetSymbolAddress((void**)&d_Gh,  g_Gh);
    float* d_fast = nullptr; cudaGetSymbolAddress((void**)&d_fast, g_fast);
    float* d_part = nullptr; cudaGetSymbolAddress((void**)&d_part, g_part);

    static bool attr_set = false;
    if (!attr_set) {
        cudaFuncSetAttribute(gemm_h,  cudaFuncAttributeMaxDynamicSharedMemorySize, HSMEM);
        cudaFuncSetAttribute(gemm_gh, cudaFuncAttributeMaxDynamicSharedMemorySize, GSMEM);
        attr_set = true;
    }

    cvt_h_kernel<<<4096, 256>>>((const float2*)x,     (__half2*)d_xh,  BATCH * D / 2);
    cvt_h_kernel<<<512,  256>>>((const float2*)Wslow, (__half2*)d_wsh, D * D / 2);
    cvt_h_kernel<<<512,  256>>>((const float2*)Wfast, (__half2*)d_wfh, D * D / 2);

    // slow = x @ Wslow^T ; fast = x @ Wfast^T
    gemm_h<<<dim3(8, 128), 128, HSMEM>>>(d_xh, d_wsh, slow,   D, D, 0);
    gemm_h<<<dim3(8, 128), 128, HSMEM>>>(d_xh, d_wfh, d_fast, D, D, 0);

    msq_stageA<<<dim3(4, 64), 256>>>();
    msq_stageB<<<4, 256>>>();
    efflr_kernel<<<1, 256>>>(plast);

    // G = x^T x : lower-triangle tiles (36 pairs), split-K over batch
    gemm_gh<<<dim3(36, 1, GSPLIT), 128, GSMEM>>>(d_xh);
    greduce_kernel<<<4096, 256>>>();

    // hebb = Wf @ G (G symmetric), split-K 4 into g_part
    gemm_h<<<dim3(8, 8, HSPLIT), 128, HSMEM>>>(d_wfh, d_Gh, d_part,
                                               D, D / HSPLIT, (long long)D * D);

    finalize_w<<<1024, 256>>>(Wfast, wnew);
    ln_kernel<<<16384, 256>>>(slow, alpha, gamma, beta, out);
}

// round 16
// speedup vs baseline: 2.0092x; 1.0061x over previous
#include <cuda_runtime.h>
#include <cuda_fp16.h>
#include <cstdint>

#define BATCH 16384
#define D     1024
#define LN_EPS 1e-5f
#define GSPLIT 8          // split-K for G = x^T x
#define HSPLIT 4          // split-K for hebb = Wf * G

// ---------------- scratch (static device globals; no runtime alloc) ----------
__device__ __align__(16) __half g_xh [(size_t)BATCH * D];     // x in fp16
__device__ __align__(16) __half g_wsh[(size_t)D * D];         // W_slow fp16
__device__ __align__(16) __half g_wfh[(size_t)D * D];         // W_fast fp16
__device__ __align__(16) __half g_Gh [(size_t)D * D];         // G = x^T x, fp16
__device__ __align__(16) float  g_fast[(size_t)BATCH * D];    // fast, fp32
__device__ __align__(16) float  g_part[(size_t)GSPLIT * D * D]; // split-K partials
__device__ float g_msq_part[128 * D];                         // per-m-tile col sums of fast^2
__device__ float g_msq[D];
__device__ float g_efflr[1];

// ---------------- helpers ----------------------------------------------------
__device__ __forceinline__ void mma16(float c[4], const unsigned a[4],
                                      unsigned b0, unsigned b1) {
    asm volatile(
        "mma.sync.aligned.m16n8k16.row.col.f32.f16.f16.f32 "
        "{%0,%1,%2,%3}, {%4,%5,%6,%7}, {%8,%9}, {%0,%1,%2,%3};\n"
        : "+f"(c[0]), "+f"(c[1]), "+f"(c[2]), "+f"(c[3])
        : "r"(a[0]), "r"(a[1]), "r"(a[2]), "r"(a[3]), "r"(b0), "r"(b1));
}

#define LDSM4(r0,r1,r2,r3,addr) \
    asm volatile("ldmatrix.sync.aligned.m8n8.x4.shared.b16 {%0,%1,%2,%3}, [%4];" \
                 : "=r"(r0),"=r"(r1),"=r"(r2),"=r"(r3) : "r"(addr))
#define LDSM4T(r0,r1,r2,r3,addr) \
    asm volatile("ldmatrix.sync.aligned.m8n8.x4.trans.shared.b16 {%0,%1,%2,%3}, [%4];" \
                 : "=r"(r0),"=r"(r1),"=r"(r2),"=r"(r3) : "r"(addr))

__device__ __forceinline__ void cpa16_s(unsigned sdst, const void* src) {
    asm volatile("cp.async.cg.shared.global [%0], [%1], 16;\n" :: "r"(sdst), "l"(src));
}
#define CP_COMMIT() asm volatile("cp.async.commit_group;\n" ::: "memory")
#define CP_WAIT0()  asm volatile("cp.async.wait_group 0;\n" ::: "memory")
#define CP_WAIT1()  asm volatile("cp.async.wait_group 1;\n" ::: "memory")

__device__ __forceinline__ float warpSum(float v) {
    #pragma unroll
    for (int o = 16; o > 0; o >>= 1) v += __shfl_xor_sync(0xffffffffu, v, o);
    return v;
}

// smem swizzles (16B chunk c within row r), conflict-free per LDSM phase
__device__ __forceinline__ unsigned off64(int r, int c) {       // 64B-pitch rows
    return (unsigned)(r * 64 + ((c ^ ((r >> 1) & 3)) << 4));
}
__device__ __forceinline__ unsigned off256(int r, int c) {      // 256B-pitch rows
    return (unsigned)(r * 256 + (((c & 8) | ((c ^ r) & 7)) << 4));
}

// ============================================================================
// Pre-convert: fp32 -> fp16 (rn)
// ============================================================================
__global__ void cvt_h_kernel(const float2* __restrict__ s, __half2* __restrict__ d, int n2) {
    int i  = blockIdx.x * 256 + threadIdx.x;
    int st = gridDim.x * 256;
    for (; i < n2; i += st) {
        float2 v = s[i];
        d[i] = __floats2half2_rn(v.x, v.y);
    }
}

// ============================================================================
// fp16 TN GEMM: C[m][n] = sum_k A[m][k] * B[n][k], fp32 accum.
// 128x128 CTA tile, 8 warps (2x4 of 64x32), BK=32, 3-stage cp.async ring,
// ldmatrix.x4, m16n8k16. 256 thr, 2 CTAs/SM -> 4 warps/SMSP (latency hiding).
// do_msq=1: epilogue also emits per-(m-tile, col) partial sums of C^2 into
// g_msq_part (zero atomics: CTA owns its (by, n0..n0+127) slice).
// ============================================================================
#define HSTAGE_A 8192               // 128 rows * 64B
#define HSTAGE   (2 * HSTAGE_A)     // 16 KB (A + B)
#define HSMEM    (3 * HSTAGE)       // 48 KB

__global__ __launch_bounds__(256, 2)
void gemm_h(const __half* __restrict__ A, const __half* __restrict__ B,
            float* __restrict__ C, int ldk, int kchunk, long long czstride,
            int do_msq) {
    extern __shared__ char dynsm[];
    __shared__ float sm_ms[2][128];
    unsigned dbase = (unsigned)__cvta_generic_to_shared(dynsm);

    const int tid  = threadIdx.x;
    const int warp = tid >> 5, lane = tid & 31;
    const int g = lane >> 2, tg = lane & 3;
    const int wm = (warp >> 2) * 64, wn = (warp & 3) * 32;
    const int m0 = blockIdx.y * 128, n0 = blockIdx.x * 128;
    const int kbase = blockIdx.z * kchunk;

    const __half* __restrict__ Ab = A + (size_t)m0 * ldk + kbase;
    const __half* __restrict__ Bb = B + (size_t)n0 * ldk + kbase;

    float acc[4][4][4];
    #pragma unroll
    for (int i = 0; i < 4; i++)
        #pragma unroll
        for (int j = 0; j < 4; j++)
            #pragma unroll
            for (int q2 = 0; q2 < 4; q2++) acc[i][j][q2] = 0.f;

    // ldmatrix base addresses; im/p enter as +1024*i (swizzle-invariant: +16 rows)
    const int q = lane >> 3, rr = lane & 7;
    unsigned abase[2], bbase[2];
    #pragma unroll
    for (int ks = 0; ks < 2; ks++) {
        abase[ks] = off64(wm + (q & 1) * 8 + rr, ks * 2 + (q >> 1));
        bbase[ks] = HSTAGE_A + off64(wn + (q >> 1) * 8 + rr, ks * 2 + (q & 1));
    }

    auto LOAD = [&](int st, int k0) {
        unsigned sa = dbase + (unsigned)(st % 3) * HSTAGE;
        #pragma unroll
        for (int i = 0; i < 2; i++) {
            int idx = tid + i * 256;
            int r = idx >> 2, c = idx & 3;
            cpa16_s(sa + off64(r, c),            Ab + (size_t)r * ldk + k0 + c * 8);
            cpa16_s(sa + HSTAGE_A + off64(r, c), Bb + (size_t)r * ldk + k0 + c * 8);
        }
    };

    const int NS = kchunk / 32;
    LOAD(0, 0);  CP_COMMIT();
    LOAD(1, 32); CP_COMMIT();

    for (int s = 0; s < NS; s++) {
        if (s == NS - 1) { CP_WAIT0(); } else { CP_WAIT1(); }
        __syncthreads();
        if (s + 2 < NS) { LOAD(s + 2, (s + 2) * 32); CP_COMMIT(); }

        unsigned sbase = dbase + (unsigned)(s % 3) * HSTAGE;
        #pragma unroll
        for (int ks = 0; ks < 2; ks++) {
            unsigned a[4][4], b[2][4];
            #pragma unroll
            for (int im = 0; im < 4; im++)
                LDSM4(a[im][0], a[im][1], a[im][2], a[im][3],
                      sbase + abase[ks] + im * 1024u);
            #pragma unroll
            for (int p = 0; p < 2; p++)
                LDSM4(b[p][0], b[p][1], b[p][2], b[p][3],
                      sbase + bbase[ks] + p * 1024u);
            #pragma unroll
            for (int im = 0; im < 4; im++)
                #pragma unroll
                for (int jn = 0; jn < 4; jn++)
                    mma16(acc[im][jn], a[im], b[jn >> 1][(jn & 1) * 2],
                          b[jn >> 1][(jn & 1) * 2 + 1]);
        }
    }

    float* Cz = C + (size_t)blockIdx.z * czstride;
    #pragma unroll
    for (int im = 0; im < 4; im++) {
        int m = m0 + wm + im * 16 + g;
        #pragma unroll
        for (int jn = 0; jn < 4; jn++) {
            int n = n0 + wn + jn * 8 + tg * 2;
            *(float2*)(Cz + (size_t)m * D + n)       = make_float2(acc[im][jn][0], acc[im][jn][1]);
            *(float2*)(Cz + (size_t)(m + 8) * D + n) = make_float2(acc[im][jn][2], acc[im][jn][3]);
        }
    }

    if (do_msq) {
        // per-thread col sums of squares over this CTA's 128 m-rows
        #pragma unroll
        for (int jn = 0; jn < 4; jn++) {
            float s0 = 0.f, s1 = 0.f;
            #pragma unroll
            for (int im = 0; im < 4; im++) {
                s0 += acc[im][jn][0] * acc[im][jn][0] + acc[im][jn][2] * acc[im][jn][2];
                s1 += acc[im][jn][1] * acc[im][jn][1] + acc[im][jn][3] * acc[im][jn][3];
            }
            // reduce over g lanes (bits 2..4)
            #pragma unroll
            for (int o = 16; o >= 4; o >>= 1) {
                s0 += __shfl_xor_sync(0xffffffffu, s0, o);
                s1 += __shfl_xor_sync(0xffffffffu, s1, o);
            }
            if (lane < 4) {
                sm_ms[warp >> 2][wn + jn * 8 + lane * 2]     = s0;
                sm_ms[warp >> 2][wn + jn * 8 + lane * 2 + 1] = s1;
            }
        }
        __syncthreads();
        if (tid < 128)
            g_msq_part[(size_t)blockIdx.y * D + n0 + tid] =
                sm_ms[0][tid] + sm_ms[1][tid];
    }
}

// ============================================================================
// G = x^T x (fp16, ldmatrix.trans on natural [k][m] layout, no transpose).
// 128x128 CTA tile, 8 warps of 64x32, BK=32, 3-stage ring, 256 thr, 2 CTAs/SM.
// blockIdx.x = lower-triangle tile pair (36); blockIdx.z = split (8).
// ============================================================================
#define GSTAGE_A 8192               // 32 rows * 256B
#define GSTAGE   (2 * GSTAGE_A)     // 16 KB
#define GSMEM    (3 * GSTAGE)       // 48 KB

__global__ __launch_bounds__(256, 2)
void gemm_gh(const __half* __restrict__ X) {
    extern __shared__ char dynsm[];
    unsigned dbase = (unsigned)__cvta_generic_to_shared(dynsm);

    const int tid  = threadIdx.x;
    const int warp = tid >> 5, lane = tid & 31;
    const int g = lane >> 2, tg = lane & 3;
    const int wm = (warp >> 2) * 64, wn = (warp & 3) * 32;

    int t = blockIdx.x;
    int bi = 0;
    while ((bi + 1) * (bi + 2) / 2 <= t) bi++;
    int bj = t - bi * (bi + 1) / 2;
    const int m0 = bi * 128, n0 = bj * 128;
    const int kbase = blockIdx.z * (BATCH / GSPLIT);   // 2048 per split

    float acc[4][4][4];
    #pragma unroll
    for (int i = 0; i < 4; i++)
        #pragma unroll
        for (int j = 0; j < 4; j++)
            #pragma unroll
            for (int q2 = 0; q2 < 4; q2++) acc[i][j][q2] = 0.f;

    const int q = lane >> 3, rr = lane & 7;
    unsigned aoff[2][4], boff[2][2];
    #pragma unroll
    for (int ks = 0; ks < 2; ks++) {
        #pragma unroll
        for (int im = 0; im < 4; im++) {
            int r = ks * 16 + (q >> 1) * 8 + rr;           // stored row = k
            int c = (wm >> 3) + im * 2 + (q & 1);          // stored chunk = m/8
            aoff[ks][im] = off256(r, c);
        }
        #pragma unroll
        for (int p = 0; p < 2; p++) {
            int r = ks * 16 + (q & 1) * 8 + rr;
            int c = (wn >> 3) + p * 2 + (q >> 1);
            boff[ks][p] = GSTAGE_A + off256(r, c);
        }
    }

    auto LOAD = [&](int st, int k0) {
        unsigned sa = dbase + (unsigned)(st % 3) * GSTAGE;
        const __half* xr = X + (size_t)(kbase + k0) * D;
        #pragma unroll
        for (int i = 0; i < 2; i++) {
            int idx = tid + i * 256;
            int r = idx >> 4, c = idx & 15;
            cpa16_s(sa + off256(r, c),            xr + (size_t)r * D + m0 + c * 8);
            cpa16_s(sa + GSTAGE_A + off256(r, c), xr + (size_t)r * D + n0 + c * 8);
        }
    };

    const int NS = (BATCH / GSPLIT) / 32;  // 64
    LOAD(0, 0);  CP_COMMIT();
    LOAD(1, 32); CP_COMMIT();

    for (int s = 0; s < NS; s++) {
        if (s == NS - 1) { CP_WAIT0(); } else { CP_WAIT1(); }
        __syncthreads();
        if (s + 2 < NS) { LOAD(s + 2, (s + 2) * 32); CP_COMMIT(); }

        unsigned sbase = dbase + (unsigned)(s % 3) * GSTAGE;
        #pragma unroll
        for (int ks = 0; ks < 2; ks++) {
            unsigned a[4][4], b[2][4];
            #pragma unroll
            for (int im = 0; im < 4; im++)
                LDSM4T(a[im][0], a[im][1], a[im][2], a[im][3], sbase + aoff[ks][im]);
            #pragma unroll
            for (int p = 0; p < 2; p++)
                LDSM4T(b[p][0], b[p][1], b[p][2], b[p][3], sbase + boff[ks][p]);
            #pragma unroll
            for (int im = 0; im < 4; im++)
                #pragma unroll
                for (int jn = 0; jn < 4; jn++)
                    mma16(acc[im][jn], a[im], b[jn >> 1][(jn & 1) * 2],
                          b[jn >> 1][(jn & 1) * 2 + 1]);
        }
    }

    float* Cp = (float*)g_part + (size_t)blockIdx.z * D * D;
    #pragma unroll
    for (int im = 0; im < 4; im++) {
        int m = m0 + wm + im * 16 + g;
        #pragma unroll
        for (int jn = 0; jn < 4; jn++) {
            int n = n0 + wn + jn * 8 + tg * 2;
            *(float2*)(Cp + (size_t)m * D + n)       = make_float2(acc[im][jn][0], acc[im][jn][1]);
            *(float2*)(Cp + (size_t)(m + 8) * D + n) = make_float2(acc[im][jn][2], acc[im][jn][3]);
        }
    }
}

// ============================================================================
// Reduce G split-K partials with symmetry mirror; round to fp16.
// ============================================================================
__global__ void greduce_kernel() {
    int i = blockIdx.x * 256 + threadIdx.x;        // grid 4096 -> 1M elements
    int r = i >> 10, c = i & 1023;
    size_t src = ((r >> 7) >= (c >> 7)) ? ((size_t)r * D + c) : ((size_t)c * D + r);
    float s = 0.f;
    #pragma unroll
    for (int z = 0; z < GSPLIT; z++) s += g_part[(size_t)z * D * D + src];
    g_Gh[i] = __float2half_rn(s);
}

// ============================================================================
// mean(fast^2) finish: sum 128 per-m-tile partials per column
// ============================================================================
__global__ void msq_stageB() {
    int c = blockIdx.x * 256 + threadIdx.x;      // grid.x = 4
    float s = 0.f;
    #pragma unroll 8
    for (int j = 0; j < 128; j++) s += g_msq_part[(size_t)j * D + c];
    g_msq[c] = s * (1.0f / (float)BATCH);
}

// ============================================================================
// eff_lr = mean(plasticity) * 0.1
// ============================================================================
__global__ void efflr_kernel(const float* __restrict__ p) {
    int t = threadIdx.x;
    float s = 0.f;
    for (int j = t; j < BATCH; j += 256) s += p[j];
    s = warpSum(s);
    __shared__ float sh[8];
    if ((t & 31) == 0) sh[t >> 5] = s;
    __syncthreads();
    if (t == 0) {
        float tot = 0.f;
        #pragma unroll
        for (int i = 0; i < 8; i++) tot += sh[i];
        g_efflr[0] = tot * (0.1f / (float)BATCH);
    }
}

// ============================================================================
// W_fast_new = W_fast + tanh(hebb/B - msq[o]*W_fast) * eff_lr
// ============================================================================
__global__ __launch_bounds__(256)
void finalize_w(const float* __restrict__ Wf, float* __restrict__ wnew) {
    int o = blockIdx.x;
    float msq = g_msq[o];
    float lr  = g_efflr[0];
    for (int j = threadIdx.x; j < D; j += 256) {
        size_t i = (size_t)o * D + j;
        float h = 0.f;
        #pragma unroll
        for (int z = 0; z < HSPLIT; z++) h += g_part[(size_t)z * D * D + i];
        float wf = Wf[i];
        wnew[i] = wf + tanhf(h * (1.0f / (float)BATCH) - msq * wf) * lr;
    }
}

// ============================================================================
// LayerNorm over combined = slow + alpha*fast; one block per row
// ============================================================================
__global__ __launch_bounds__(256)
void ln_kernel(const float* __restrict__ slow, const float* __restrict__ alpha,
               const float* __restrict__ gamma, const float* __restrict__ beta,
               float* __restrict__ out) {
    int r = blockIdx.x, t = threadIdx.x;
    const float a = alpha[0];
    float4 s4 = ((const float4*)(slow + (size_t)r * D))[t];
    float4 f4 = ((const float4*)((const float*)g_fast + (size_t)r * D))[t];
    float4 v;
    v.x = s4.x + a * f4.x; v.y = s4.y + a * f4.y;
    v.z = s4.z + a * f4.z; v.w = s4.w + a * f4.w;

    float sum = (v.x + v.y) + (v.z + v.w);
    float sq  = (v.x * v.x + v.y * v.y) + (v.z * v.z + v.w * v.w);
    sum = warpSum(sum); sq = warpSum(sq);

    __shared__ float sh[16];
    int w = t >> 5, l = t & 31;
    if (l == 0) { sh[w] = sum; sh[8 + w] = sq; }
    __syncthreads();
    if (t == 0) {
        float s = 0.f, qq = 0.f;
        #pragma unroll
        for (int i = 0; i < 8; i++) { s += sh[i]; qq += sh[8 + i]; }
        sh[0] = s; sh[8] = qq;
    }
    __syncthreads();
    float mu  = sh[0] * (1.0f / (float)D);
    float var = sh[8] * (1.0f / (float)D) - mu * mu;
    float rs  = rsqrtf(var + LN_EPS);

    float4 g4 = ((const float4*)gamma)[t];
    float4 b4 = ((const float4*)beta)[t];
    float4 o4;
    o4.x = (v.x - mu) * rs * g4.x + b4.x;
    o4.y = (v.y - mu) * rs * g4.y + b4.y;
    o4.z = (v.z - mu) * rs * g4.z + b4.z;
    o4.w = (v.w - mu) * rs * g4.w + b4.w;
    ((float4*)(out + (size_t)r * D))[t] = o4;
}

// ============================================================================
extern "C" void kernel_launch(void* const* d_in, const int* in_sizes, int n_in,
                              void* d_out, int out_size) {
    (void)in_sizes; (void)n_in; (void)out_size;
    const float* x     = (const float*)d_in[0];
    const float* plast = (const float*)d_in[1];
    const float* alpha = (const float*)d_in[2];
    const float* Wslow = (const float*)d_in[3];
    const float* Wfast = (const float*)d_in[4];
    const float* gamma = (const float*)d_in[5];
    const float* beta  = (const float*)d_in[6];

    float* out  = (float*)d_out;                 // [16384, 1024]
    float* slow = out  + (size_t)BATCH * D;      // [16384, 1024]
    float* wnew = slow + (size_t)BATCH * D;      // [1024, 1024]

    __half* d_xh  = nullptr; cudaGetSymbolAddress((void**)&d_xh,  g_xh);
    __half* d_wsh = nullptr; cudaGetSymbolAddress((void**)&d_wsh, g_wsh);
    __half* d_wfh = nullptr; cudaGetSymbolAddress((void**)&d_wfh, g_wfh);
    __half* d_Gh  = nullptr; cudaGetSymbolAddress((void**)&d_Gh,  g_Gh);
    float* d_fast = nullptr; cudaGetSymbolAddress((void**)&d_fast, g_fast);
    float* d_part = nullptr; cudaGetSymbolAddress((void**)&d_part, g_part);

    static bool attr_set = false;
    if (!attr_set) {
        cudaFuncSetAttribute(gemm_h,  cudaFuncAttributeMaxDynamicSharedMemorySize, HSMEM);
        cudaFuncSetAttribute(gemm_gh, cudaFuncAttributeMaxDynamicSharedMemorySize, GSMEM);
        attr_set = true;
    }

    cvt_h_kernel<<<4096, 256>>>((const float2*)x,     (__half2*)d_xh,  BATCH * D / 2);
    cvt_h_kernel<<<512,  256>>>((const float2*)Wslow, (__half2*)d_wsh, D * D / 2);
    cvt_h_kernel<<<512,  256>>>((const float2*)Wfast, (__half2*)d_wfh, D * D / 2);

    // slow = x @ Wslow^T ; fast = x @ Wfast^T (+ fused msq partials)
    gemm_h<<<dim3(8, 128), 256, HSMEM>>>(d_xh, d_wsh, slow,   D, D, 0, 0);
    gemm_h<<<dim3(8, 128), 256, HSMEM>>>(d_xh, d_wfh, d_fast, D, D, 0, 1);

    msq_stageB<<<4, 256>>>();
    efflr_kernel<<<1, 256>>>(plast);

    // G = x^T x : lower-triangle tiles (36 pairs), split-K over batch
    gemm_gh<<<dim3(36, 1, GSPLIT), 256, GSMEM>>>(d_xh);
    greduce_kernel<<<4096, 256>>>();

    // hebb = Wf @ G (G symmetric), split-K 4 into g_part
    gemm_h<<<dim3(8, 8, HSPLIT), 256, HSMEM>>>(d_wfh, d_Gh, d_part,
                                               D, D / HSPLIT, (long long)D * D, 0);

    finalize_w<<<1024, 256>>>(Wfast, wnew);
    ln_kernel<<<16384, 256>>>(slow, alpha, gamma, beta, out);
}